// round 16
// baseline (speedup 1.0000x reference)
#include <cuda_runtime.h>
#include <cuda_fp16.h>
#include <math.h>
#include <stdint.h>

#define H1 128
#define H2 256
#define NCLS 16
#define MAXN 65536
#define MAXE 1048576

// ---- scratch (device globals: allocation-free per harness rules) ----
__device__ __align__(16) __half g_xh[MAXN * H1];      // x in fp16 (gemm1 byproduct)
__device__ __align__(16) __half g_y[MAXN * H1];       // relu(x@Wp^T+bp)
__device__ __align__(16) __half g_wsh[H1 * H1];       // fp16 weights
__device__ __align__(16) __half g_wnh[H1 * H1];
__device__ __align__(16) __half g_w1h[H2 * H1];
__device__ __align__(16) int g_hist[MAXN];
__device__ __align__(16) int g_offs[MAXN + 4];
__device__ __align__(16) int g_cursor[MAXN];
__device__ __align__(16) int g_ssrc[MAXE];

__device__ __forceinline__ void mma_f16(
    float* c, const uint32_t* a, const uint32_t* b)
{
    asm volatile(
        "mma.sync.aligned.m16n8k16.row.col.f32.f16.f16.f32 "
        "{%0,%1,%2,%3}, {%4,%5,%6,%7}, {%8,%9}, {%0,%1,%2,%3};\n"
        : "+f"(c[0]), "+f"(c[1]), "+f"(c[2]), "+f"(c[3])
        : "r"(a[0]), "r"(a[1]), "r"(a[2]), "r"(a[3]),
          "r"(b[0]), "r"(b[1]));
}

__device__ __forceinline__ void ldsm_x4(
    uint32_t& r0, uint32_t& r1, uint32_t& r2, uint32_t& r3, uint32_t addr)
{
    asm volatile(
        "ldmatrix.sync.aligned.m8n8.x4.shared.b16 {%0,%1,%2,%3}, [%4];"
        : "=r"(r0), "=r"(r1), "=r"(r2), "=r"(r3) : "r"(addr));
}

#define CP_ASYNC16(dst, src) \
    asm volatile("cp.async.cg.shared.global [%0], [%1], 16;" \
                 :: "r"(dst), "l"(src))
#define CP_COMMIT() asm volatile("cp.async.commit_group;")

// weights-only fp32 -> fp16 (Ws, Wn, W1): 16384 float4 chunks total
__global__ void conv_w(
    const float4* __restrict__ ws, const float4* __restrict__ wn,
    const float4* __restrict__ w1,
    uint2* __restrict__ wsh, uint2* __restrict__ wnh, uint2* __restrict__ w1h)
{
    int i = blockIdx.x * blockDim.x + threadIdx.x;
    const float4* in;
    uint2* out;
    int j = i;
    if      (j < 4096)  { in = ws; out = wsh; }
    else if (j < 8192)  { in = wn; out = wnh; j -= 4096; }
    else if (j < 16384) { in = w1; out = w1h; j -= 8192; }
    else return;
    float4 v = in[j];
    __half2 a = __floats2half2_rn(v.x, v.y);
    __half2 b = __floats2half2_rn(v.z, v.w);
    uint2 o;
    o.x = *(uint32_t*)&a;
    o.y = *(uint32_t*)&b;
    out[j] = o;
}

// ============================================================================
// GEMM1 (fused conversion): reads fp32 x and Wp, converts to fp16 during
// staging, emits xh (fp16 x) as a byproduct of A-staging, computes
//   y = relu(x @ Wp^T + bp)   [128-row block, N=K=128]
// 256 threads = 8 warps (2M x 4N). Static smem 32KB (two 128x64-half tiles).
// ============================================================================
__global__ void __launch_bounds__(256) gemm1_fused(
    const float* __restrict__ X, const float* __restrict__ Wp,
    const float* __restrict__ bp, __half* __restrict__ Y,
    __half* __restrict__ XH, int M)
{
    __shared__ __align__(16) char smem[32768];
    const uint32_t sbase = (uint32_t)__cvta_generic_to_shared(smem);
    const int K = 128;

    const int tid  = threadIdx.x;
    const int lane = tid & 31;
    const int warp = tid >> 5;
    const int wm = (warp & 1) * 64;
    const int wn = (warp >> 1) * 32;
    const int m0 = blockIdx.x * 128;
    const int g  = lane >> 2;
    const int tg = lane & 3;

    float acc[4][4][4];
    #pragma unroll
    for (int mi = 0; mi < 4; mi++)
        #pragma unroll
        for (int ni = 0; ni < 4; ni++)
            #pragma unroll
            for (int c = 0; c < 4; c++) acc[mi][ni][c] = 0.0f;

    #pragma unroll
    for (int t = 0; t < 2; t++) {
        const int k0 = t * 64;
        __syncthreads();                      // protect smem from prior compute
        // stage A (x, fp32->fp16, + write xh) and B (Wp, fp32->fp16)
        #pragma unroll
        for (int it = 0; it < 8; it++) {
            int f = it * 256 + tid;           // float4 chunk: 4 halfs = 8B
            int r = f >> 4, c4 = f & 15;
            uint32_t soff = (uint32_t)(r * 128 + (((c4 >> 1) ^ (r & 7)) << 4)
                                       + (c4 & 1) * 8);
            float4 va = *reinterpret_cast<const float4*>(
                X + (size_t)(m0 + r) * K + k0 + c4 * 4);
            __half2 a01 = __floats2half2_rn(va.x, va.y);
            __half2 a23 = __floats2half2_rn(va.z, va.w);
            uint2 oa;
            oa.x = *(uint32_t*)&a01;
            oa.y = *(uint32_t*)&a23;
            *reinterpret_cast<uint2*>(smem + soff) = oa;
            *reinterpret_cast<uint2*>(XH + (size_t)(m0 + r) * K + k0 + c4 * 4) = oa;
            float4 vb = *reinterpret_cast<const float4*>(
                Wp + (size_t)r * K + k0 + c4 * 4);
            __half2 b01 = __floats2half2_rn(vb.x, vb.y);
            __half2 b23 = __floats2half2_rn(vb.z, vb.w);
            uint2 ob;
            ob.x = *(uint32_t*)&b01;
            ob.y = *(uint32_t*)&b23;
            *reinterpret_cast<uint2*>(smem + 16384 + soff) = ob;
        }
        __syncthreads();

        const uint32_t abase = sbase;
        const uint32_t bbase = sbase + 16384;
        #pragma unroll
        for (int ks = 0; ks < 4; ks++) {
            const int kk = ks * 16;
            const int kcA = (kk >> 3) + (lane >> 4);
            const uint32_t aswz = (uint32_t)((kcA ^ (lane & 7)) << 4);
            uint32_t af[4][4];
            #pragma unroll
            for (int mi = 0; mi < 4; mi++)
                ldsm_x4(af[mi][0], af[mi][1], af[mi][2], af[mi][3],
                        abase + (uint32_t)((wm + mi * 16 + (lane & 15)) * 128)
                              + aswz);
            const int kcB = (kk >> 3) + ((lane >> 3) & 1);
            const uint32_t bswz = (uint32_t)((kcB ^ (lane & 7)) << 4);
            const int brow = wn + ((lane >> 4) & 1) * 8 + (lane & 7);
            uint32_t bf[4][2];
            #pragma unroll
            for (int nip = 0; nip < 2; nip++) {
                uint32_t r0, r1, r2, r3;
                ldsm_x4(r0, r1, r2, r3,
                        bbase + (uint32_t)((brow + nip * 16) * 128) + bswz);
                bf[2 * nip][0] = r0;     bf[2 * nip][1] = r1;
                bf[2 * nip + 1][0] = r2; bf[2 * nip + 1][1] = r3;
            }
            #pragma unroll
            for (int mi = 0; mi < 4; mi++)
                #pragma unroll
                for (int ni = 0; ni < 4; ni++)
                    mma_f16(acc[mi][ni], af[mi], bf[ni]);
        }
    }

    // epilogue: relu + bias -> Y (fp16)
    #pragma unroll
    for (int mi = 0; mi < 4; mi++) {
        const int r0 = m0 + wm + mi * 16 + g;
        #pragma unroll
        for (int ni = 0; ni < 4; ni++) {
            const int col = wn + ni * 8 + tg * 2;
            const float b0 = bp[col], b1 = bp[col + 1];
            float v0 = fmaxf(acc[mi][ni][0] + b0, 0.f);
            float v1 = fmaxf(acc[mi][ni][1] + b1, 0.f);
            float v2 = fmaxf(acc[mi][ni][2] + b0, 0.f);
            float v3 = fmaxf(acc[mi][ni][3] + b1, 0.f);
            *reinterpret_cast<__half2*>(Y + (size_t)r0 * H1 + col) =
                __floats2half2_rn(v0, v1);
            *reinterpret_cast<__half2*>(Y + (size_t)(r0 + 8) * H1 + col) =
                __floats2half2_rn(v2, v3);
        }
    }
}

// ============================================================================
// FUSED TAIL: per 128-row block:
//   Phase 0: p_s[r] = segmax over bucketed edges of y[src]  -> smem (swizzled)
//   Phase A: h   = leaky(x@Ws^T + p_s@Wn^T + bn)            -> smem h_s
//   Phase B: h2  = leaky(h_s@W1^T + b1)                     -> smem h2s
//   Phase C: out = sigmoid(h2s@W2^T + b2)                   -> gmem fp32
// 512 threads = 16 warps. Dyn smem 133120 B (layout per R12).
// ============================================================================
__global__ void __launch_bounds__(512) fused_tail(
    const __half* __restrict__ X,  const __half* __restrict__ Wsh,
    const __half* __restrict__ Wnh, const float* __restrict__ bn,
    const __half* __restrict__ W1h, const float* __restrict__ b1v,
    const float* __restrict__ W2,  const float* __restrict__ b2v,
    const uint2* __restrict__ Y,   const int* __restrict__ offs,
    const int* __restrict__ ssrc,  float* __restrict__ out, int M)
{
    extern __shared__ __align__(16) char dsm[];
    const uint32_t sbase = (uint32_t)__cvta_generic_to_shared(dsm);
    const int R1 = 34816, R2 = 67584, R3 = 100352;
    const int K = 128;

    const int tid  = threadIdx.x;
    const int lane = tid & 31;
    const int warp = tid >> 5;
    const int m0 = blockIdx.x * 128;
    const int g  = lane >> 2;
    const int tg = lane & 3;

    auto stage128 = [&](uint32_t base, const __half* G) {
        #pragma unroll
        for (int it = 0; it < 4; it++) {
            int f = it * 512 + tid;
            int r = f >> 4, c = f & 15;
            uint32_t soff = (uint32_t)(r * 256 + ((c ^ (r & 7)) << 4));
            CP_ASYNC16(base + soff, G + (size_t)r * K + c * 8);
        }
    };

    stage128(sbase + R1, X + (size_t)m0 * K);
    stage128(sbase + R2, Wsh);
    stage128(sbase + R3, Wnh);
    CP_COMMIT();

    // ---- Phase 0: gather segmented max into p_s (overlaps cp.async) ----
    {
        const __half2 z = __float2half2_rn(0.f);
        for (int i = 0; i < 8; i++) {
            int r = warp * 8 + i;
            int n = m0 + r;
            int e = offs[n], end = offs[n + 1];
            __half2 a = z, b = z;
            for (; e + 7 < end; e += 8) {
                uint2 v[8];
                #pragma unroll
                for (int j = 0; j < 8; j++)
                    v[j] = Y[(size_t)ssrc[e + j] * 32 + lane];
                #pragma unroll
                for (int j = 0; j < 8; j++) {
                    a = __hmax2(a, *(__half2*)&v[j].x);
                    b = __hmax2(b, *(__half2*)&v[j].y);
                }
            }
            for (; e + 3 < end; e += 4) {
                uint2 v0 = Y[(size_t)ssrc[e]     * 32 + lane];
                uint2 v1 = Y[(size_t)ssrc[e + 1] * 32 + lane];
                uint2 v2 = Y[(size_t)ssrc[e + 2] * 32 + lane];
                uint2 v3 = Y[(size_t)ssrc[e + 3] * 32 + lane];
                a = __hmax2(a, __hmax2(
                        __hmax2(*(__half2*)&v0.x, *(__half2*)&v1.x),
                        __hmax2(*(__half2*)&v2.x, *(__half2*)&v3.x)));
                b = __hmax2(b, __hmax2(
                        __hmax2(*(__half2*)&v0.y, *(__half2*)&v1.y),
                        __hmax2(*(__half2*)&v2.y, *(__half2*)&v3.y)));
            }
            for (; e < end; e++) {
                uint2 v0 = Y[(size_t)ssrc[e] * 32 + lane];
                a = __hmax2(a, *(__half2*)&v0.x);
                b = __hmax2(b, *(__half2*)&v0.y);
            }
            uint32_t off = (uint32_t)(r * 256 + (((lane >> 1) ^ (r & 7)) << 4)
                                      + (lane & 1) * 8);
            uint2 o;
            o.x = *(uint32_t*)&a;
            o.y = *(uint32_t*)&b;
            *reinterpret_cast<uint2*>(dsm + off) = o;
        }
    }
    asm volatile("cp.async.wait_group 0;");
    __syncthreads();

    // ---- Phase A: 16 warps (4M x 4N), 32x32 per warp, two passes ----
    const int wmA = (warp & 3) * 32;
    const int wnA = (warp >> 2) * 32;

    float acc[2][4][4];
    #pragma unroll
    for (int mi = 0; mi < 2; mi++)
        #pragma unroll
        for (int ni = 0; ni < 4; ni++)
            #pragma unroll
            for (int c = 0; c < 4; c++) acc[mi][ni][c] = 0.0f;

    auto do_pass = [&](uint32_t abase, uint32_t bbase) {
        #pragma unroll
        for (int ks = 0; ks < 8; ks++) {
            const int kk = ks * 16;
            const int kcA = (kk >> 3) + (lane >> 4);
            const uint32_t aswz = (uint32_t)((kcA ^ (lane & 7)) << 4);
            uint32_t af[2][4];
            #pragma unroll
            for (int mi = 0; mi < 2; mi++)
                ldsm_x4(af[mi][0], af[mi][1], af[mi][2], af[mi][3],
                        abase + (uint32_t)((wmA + mi * 16 + (lane & 15)) * 256)
                              + aswz);
            const int kcB = (kk >> 3) + ((lane >> 3) & 1);
            const uint32_t bswz = (uint32_t)((kcB ^ (lane & 7)) << 4);
            const int brow = wnA + ((lane >> 4) & 1) * 8 + (lane & 7);
            uint32_t bf[4][2];
            #pragma unroll
            for (int nip = 0; nip < 2; nip++) {
                uint32_t r0, r1, r2, r3;
                ldsm_x4(r0, r1, r2, r3,
                        bbase + (uint32_t)((brow + nip * 16) * 256) + bswz);
                bf[2 * nip][0] = r0;     bf[2 * nip][1] = r1;
                bf[2 * nip + 1][0] = r2; bf[2 * nip + 1][1] = r3;
            }
            #pragma unroll
            for (int mi = 0; mi < 2; mi++)
                #pragma unroll
                for (int ni = 0; ni < 4; ni++)
                    mma_f16(acc[mi][ni], af[mi], bf[ni]);
        }
    };

    do_pass(sbase + R1, sbase + R2);      // x @ Ws^T
    __syncthreads();                      // R1/R2 reads done everywhere
    stage128(sbase + R2, W1h);            // W1 rows 0..127
    stage128(sbase + R1, W1h + 128 * K);  // W1 rows 128..255
    CP_COMMIT();
    do_pass(sbase + 0, sbase + R3);       // pooled @ Wn^T
    __syncthreads();                      // p_s reads done before h_s writes

    // epilogue A -> h_s (stride 136 halfs, base 0)
    __half* h_s = reinterpret_cast<__half*>(dsm);
    #pragma unroll
    for (int mi = 0; mi < 2; mi++) {
        const int r0 = wmA + mi * 16 + g;
        #pragma unroll
        for (int ni = 0; ni < 4; ni++) {
            const int col = wnA + ni * 8 + tg * 2;
            const float c0 = bn[col], c1 = bn[col + 1];
            float v0 = acc[mi][ni][0] + c0;
            float v1 = acc[mi][ni][1] + c1;
            float v2 = acc[mi][ni][2] + c0;
            float v3 = acc[mi][ni][3] + c1;
            v0 = (v0 > 0.f) ? v0 : 0.01f * v0;
            v1 = (v1 > 0.f) ? v1 : 0.01f * v1;
            v2 = (v2 > 0.f) ? v2 : 0.01f * v2;
            v3 = (v3 > 0.f) ? v3 : 0.01f * v3;
            *reinterpret_cast<__half2*>(&h_s[r0 * 136 + col]) =
                __floats2half2_rn(v0, v1);
            *reinterpret_cast<__half2*>(&h_s[(r0 + 8) * 136 + col]) =
                __floats2half2_rn(v2, v3);
        }
    }
    asm volatile("cp.async.wait_group 0;");
    __syncthreads();

    // ---- Phase B: h2 = leaky(h_s @ W1^T + b1), 16 warps (2M x 8N) ----
    const int wmB = (warp & 1) * 64;
    const int wnB = (warp >> 1) * 32;
    const uint32_t w1base = (wnB < 128) ? (sbase + R2) : (sbase + R1);
    const int wrow0 = (wnB < 128) ? wnB : (wnB - 128);

    float accB[4][4][4];
    #pragma unroll
    for (int mi = 0; mi < 4; mi++)
        #pragma unroll
        for (int ni = 0; ni < 4; ni++)
            #pragma unroll
            for (int c = 0; c < 4; c++) accB[mi][ni][c] = 0.0f;

    #pragma unroll
    for (int ks = 0; ks < 8; ks++) {
        const int kk = ks * 16;
        uint32_t af[4][4];
        #pragma unroll
        for (int mi = 0; mi < 4; mi++) {
            int arow = wmB + mi * 16 + (lane & 15);
            uint32_t addr = sbase +
                (uint32_t)(arow * 136 + kk + (lane >> 4) * 8) * 2;
            ldsm_x4(af[mi][0], af[mi][1], af[mi][2], af[mi][3], addr);
        }
        const int kcB = (kk >> 3) + ((lane >> 3) & 1);
        const uint32_t bswz = (uint32_t)((kcB ^ (lane & 7)) << 4);
        const int brow = wrow0 + ((lane >> 4) & 1) * 8 + (lane & 7);
        uint32_t bf[4][2];
        #pragma unroll
        for (int nip = 0; nip < 2; nip++) {
            uint32_t r0, r1, r2, r3;
            ldsm_x4(r0, r1, r2, r3,
                    w1base + (uint32_t)((brow + nip * 16) * 256) + bswz);
            bf[2 * nip][0] = r0;     bf[2 * nip][1] = r1;
            bf[2 * nip + 1][0] = r2; bf[2 * nip + 1][1] = r3;
        }
        #pragma unroll
        for (int mi = 0; mi < 4; mi++)
            #pragma unroll
            for (int ni = 0; ni < 4; ni++)
                mma_f16(accB[mi][ni], af[mi], bf[ni]);
    }
    __syncthreads();   // h_s & W1 reads done; safe to overwrite with h2s/w2s

    __half* h2s = reinterpret_cast<__half*>(dsm);
    __half* w2s = h2s + 128 * 264;        // byte offset 67584
    #pragma unroll
    for (int mi = 0; mi < 4; mi++) {
        const int r0 = wmB + mi * 16 + g;
        #pragma unroll
        for (int ni = 0; ni < 4; ni++) {
            const int col = wnB + ni * 8 + tg * 2;
            const float c0 = b1v[col], c1 = b1v[col + 1];
            float v0 = accB[mi][ni][0] + c0;
            float v1 = accB[mi][ni][1] + c1;
            float v2 = accB[mi][ni][2] + c0;
            float v3 = accB[mi][ni][3] + c1;
            v0 = (v0 > 0.f) ? v0 : 0.01f * v0;
            v1 = (v1 > 0.f) ? v1 : 0.01f * v1;
            v2 = (v2 > 0.f) ? v2 : 0.01f * v2;
            v3 = (v3 > 0.f) ? v3 : 0.01f * v3;
            *reinterpret_cast<__half2*>(&h2s[r0 * 264 + col]) =
                __floats2half2_rn(v0, v1);
            *reinterpret_cast<__half2*>(&h2s[(r0 + 8) * 264 + col]) =
                __floats2half2_rn(v2, v3);
        }
    }
    #pragma unroll
    for (int it = 0; it < 2; it++) {
        int f = it * 512 + tid;               // 1024 float4 chunks of W2
        int crow = f >> 6;
        int k = (f & 63) * 4;
        float4 v = reinterpret_cast<const float4*>(W2)[f];
        *reinterpret_cast<__half2*>(&w2s[crow * 264 + k]) =
            __floats2half2_rn(v.x, v.y);
        *reinterpret_cast<__half2*>(&w2s[crow * 264 + k + 2]) =
            __floats2half2_rn(v.z, v.w);
    }
    __syncthreads();

    // ---- Phase C: head (warps 0..7) ----
    if (warp < 8) {
        float ao[2][4];
        #pragma unroll
        for (int ni = 0; ni < 2; ni++)
            #pragma unroll
            for (int c = 0; c < 4; c++) ao[ni][c] = 0.0f;

        const uint32_t wbb = sbase + 67584;
        const int arow = warp * 16 + (lane & 15);
        const int ahalf = (lane >> 4) * 8;
        const int brow = ((lane >> 4) & 1) * 8 + (lane & 7);
        const int bhalf = ((lane >> 3) & 1) * 8;
        #pragma unroll
        for (int ks = 0; ks < 16; ks++) {
            const int kk = ks * 16;
            uint32_t af[4];
            ldsm_x4(af[0], af[1], af[2], af[3],
                    sbase + (uint32_t)(arow * 264 + kk + ahalf) * 2);
            uint32_t r0, r1, r2, r3;
            ldsm_x4(r0, r1, r2, r3,
                    wbb + (uint32_t)(brow * 264 + kk + bhalf) * 2);
            uint32_t bf0[2] = {r0, r1}, bf1[2] = {r2, r3};
            mma_f16(ao[0], af, bf0);
            mma_f16(ao[1], af, bf1);
        }
        const int m = m0 + warp * 16 + g;
        #pragma unroll
        for (int ni = 0; ni < 2; ni++) {
            const int col = ni * 8 + tg * 2;
            const float c0 = b2v[col], c1 = b2v[col + 1];
            float s0 = 1.0f / (1.0f + expf(-(ao[ni][0] + c0)));
            float s1 = 1.0f / (1.0f + expf(-(ao[ni][1] + c1)));
            float s2 = 1.0f / (1.0f + expf(-(ao[ni][2] + c0)));
            float s3 = 1.0f / (1.0f + expf(-(ao[ni][3] + c1)));
            *reinterpret_cast<float2*>(out + (size_t)m * NCLS + col) =
                make_float2(s0, s1);
            *reinterpret_cast<float2*>(out + (size_t)(m + 8) * NCLS + col) =
                make_float2(s2, s3);
        }
    }
}

// ============================================================================
// Edge bucketing: int4-vectorized hist/scatter, int4 single-block scan
// ============================================================================
__global__ void hist_kernel(const int4* __restrict__ dst4,
                            int* __restrict__ hist, int E4)
{
    int i = blockIdx.x * blockDim.x + threadIdx.x;
    if (i < E4) {
        int4 d = dst4[i];
        atomicAdd(&hist[d.x], 1);
        atomicAdd(&hist[d.y], 1);
        atomicAdd(&hist[d.z], 1);
        atomicAdd(&hist[d.w], 1);
    }
}

__global__ void __launch_bounds__(1024) scan_kernel(
    const int4* __restrict__ h4, int* __restrict__ offs,
    int* __restrict__ cursor, int N)
{
    __shared__ int part[1024];
    const int tid = threadIdx.x;
    int s = 0;
    #pragma unroll 4
    for (int i = 0; i < 16; i++) {
        int4 h = h4[tid * 16 + i];
        s += h.x + h.y + h.z + h.w;
    }
    part[tid] = s;
    __syncthreads();
    for (int d = 1; d < 1024; d <<= 1) {
        int v = (tid >= d) ? part[tid - d] : 0;
        __syncthreads();
        part[tid] += v;
        __syncthreads();
    }
    int run = (tid == 0) ? 0 : part[tid - 1];
    #pragma unroll 4
    for (int i = 0; i < 16; i++) {
        int4 h = h4[tid * 16 + i];
        int4 o;
        o.x = run;
        o.y = o.x + h.x;
        o.z = o.y + h.y;
        o.w = o.z + h.z;
        run = o.w + h.w;
        reinterpret_cast<int4*>(offs)[tid * 16 + i] = o;
        reinterpret_cast<int4*>(cursor)[tid * 16 + i] = o;
    }
    if (tid == 1023) offs[N] = run;
}

__global__ void scatter_edges(const int4* __restrict__ src4,
                              const int4* __restrict__ dst4,
                              int* __restrict__ cursor,
                              int* __restrict__ ssrc, int E4)
{
    int i = blockIdx.x * blockDim.x + threadIdx.x;
    if (i < E4) {
        int4 s = src4[i];
        int4 d = dst4[i];
        ssrc[atomicAdd(&cursor[d.x], 1)] = s.x;
        ssrc[atomicAdd(&cursor[d.y], 1)] = s.y;
        ssrc[atomicAdd(&cursor[d.z], 1)] = s.z;
        ssrc[atomicAdd(&cursor[d.w], 1)] = s.w;
    }
}

extern "C" void kernel_launch(void* const* d_in, const int* in_sizes, int n_in,
                              void* d_out, int out_size)
{
    const float* x  = (const float*)d_in[0];
    const float* Wp = (const float*)d_in[1];
    const float* bp = (const float*)d_in[2];
    const float* Ws = (const float*)d_in[3];
    const float* Wn = (const float*)d_in[4];
    const float* bn = (const float*)d_in[5];
    const float* W1 = (const float*)d_in[6];
    const float* b1 = (const float*)d_in[7];
    const float* W2 = (const float*)d_in[8];
    const float* b2 = (const float*)d_in[9];
    const int* src  = (const int*)d_in[10];
    const int* dst  = (const int*)d_in[11];
    float* out = (float*)d_out;

    const int M = in_sizes[0] / H1;   // IN_FEATS == H1 == 128
    const int E = in_sizes[10];
    const int E4 = E / 4;

    __half *xh, *y, *wsh, *wnh, *w1h;
    int *hist, *offs, *cursor, *ssrc;
    cudaGetSymbolAddress((void**)&xh, g_xh);
    cudaGetSymbolAddress((void**)&y, g_y);
    cudaGetSymbolAddress((void**)&wsh, g_wsh);
    cudaGetSymbolAddress((void**)&wnh, g_wnh);
    cudaGetSymbolAddress((void**)&w1h, g_w1h);
    cudaGetSymbolAddress((void**)&hist, g_hist);
    cudaGetSymbolAddress((void**)&offs, g_offs);
    cudaGetSymbolAddress((void**)&cursor, g_cursor);
    cudaGetSymbolAddress((void**)&ssrc, g_ssrc);

    cudaFuncSetAttribute(fused_tail,
                         cudaFuncAttributeMaxDynamicSharedMemorySize, 133120);

    static cudaStream_t s1 = nullptr;
    static cudaEvent_t evR = nullptr, evS = nullptr;
    if (s1 == nullptr) {
        cudaStreamCreateWithFlags(&s1, cudaStreamNonBlocking);
        cudaEventCreateWithFlags(&evR, cudaEventDisableTiming);
        cudaEventCreateWithFlags(&evS, cudaEventDisableTiming);
    }

    // ---- fork: weight conversion + edge bucketing on side stream ----
    cudaEventRecord(evR, 0);
    cudaStreamWaitEvent(s1, evR, 0);
    conv_w<<<64, 256, 0, s1>>>(
        (const float4*)Ws, (const float4*)Wn, (const float4*)W1,
        (uint2*)wsh, (uint2*)wnh, (uint2*)w1h);
    cudaMemsetAsync(hist, 0, M * sizeof(int), s1);
    hist_kernel<<<(E4 + 255) / 256, 256, 0, s1>>>((const int4*)dst, hist, E4);
    scan_kernel<<<1, 1024, 0, s1>>>((const int4*)hist, offs, cursor, M);
    scatter_edges<<<(E4 + 255) / 256, 256, 0, s1>>>(
        (const int4*)src, (const int4*)dst, cursor, ssrc, E4);
    cudaEventRecord(evS, s1);

    // ---- main: gemm1 (fp32 in, fp16 out, emits xh byproduct) ----
    gemm1_fused<<<M / 128, 256>>>(x, Wp, bp, y, xh, M);

    // ---- join, then the whole rest fused ----
    cudaStreamWaitEvent(0, evS, 0);
    fused_tail<<<M / 128, 512, 133120>>>(
        xh, wsh, wnh, bn, w1h, b1, W2, b2,
        (const uint2*)y, offs, ssrc, out, M);
}